// round 2
// baseline (speedup 1.0000x reference)
#include <cuda_runtime.h>
#include <cuda_bf16.h>
#include <cstdint>

// Problem constants (fixed by the dataset)
#define NTOK 4096
#define KTOP 64
#define DIM  1024
#define NLAT 16384

// Tiling for the fused kernel
#define BN 128   // token tile
#define BD 128   // d (output col) tile
#define JT 8     // inner-dim step for skip GEMM
#define TM 8
#define TN 8

// Deterministic scratch (no device allocations allowed)
__device__ float g_colsum_part[32 * DIM];  // 32 row-chunks x 1024 cols
__device__ float g_s2_part[32 * 4];        // per-block sum(y^2) partials
__device__ float g_err_part[32 * 8];       // per-block sum(e^2) partials (grid 8x32)

// ---------------------------------------------------------------------------
// Kernel A: per-column sums of y and partial sum of y^2
// grid (4, 32), block 256. block (bx,by): cols bx*256..+255, rows by*128..+127
// ---------------------------------------------------------------------------
__global__ void colstats_kernel(const float* __restrict__ y)
{
    int d  = blockIdx.x * 256 + threadIdx.x;
    int r0 = blockIdx.y * 128;
    float s = 0.f, s2 = 0.f;
    const float* yp = y + (size_t)r0 * DIM + d;
#pragma unroll 4
    for (int r = 0; r < 128; r++) {
        float v = yp[(size_t)r * DIM];
        s += v;
        s2 += v * v;
    }
    g_colsum_part[blockIdx.y * DIM + d] = s;

    __shared__ float red[256];
    red[threadIdx.x] = s2;
    __syncthreads();
    for (int st = 128; st > 0; st >>= 1) {
        if (threadIdx.x < st) red[threadIdx.x] += red[threadIdx.x + st];
        __syncthreads();
    }
    if (threadIdx.x == 0) g_s2_part[blockIdx.y * 4 + blockIdx.x] = red[0];
}

// ---------------------------------------------------------------------------
// Kernel B: fused  out = x @ W_skip^T + gather-decode + b_dec ; err partials
// grid (DIM/BD=8, NTOK/BN=32), block 256 (16x16), 8x8 per-thread register tile
// ---------------------------------------------------------------------------
__global__ void fused_kernel(const float* __restrict__ x,
                             const float* __restrict__ y,
                             const float* __restrict__ lat_acts,
                             const int*   __restrict__ lat_idx,
                             const float* __restrict__ W_dec,
                             const float* __restrict__ b_dec,
                             const float* __restrict__ post_enc,
                             const float* __restrict__ post_enc_scale,
                             const float* __restrict__ W_skip,
                             float* __restrict__ out)
{
    __shared__ float xs[JT][BN];
    __shared__ float ws[JT][BD];
    __shared__ float acts_s[BN][32];
    __shared__ int   idx_s[BN][32];
    __shared__ float red[256];

    const int tid = threadIdx.x;
    const int tx = tid & 15;   // d group
    const int ty = tid >> 4;   // token group
    const int n0 = blockIdx.y * BN;
    const int d0 = blockIdx.x * BD;

    float c[TM][TN];
#pragma unroll
    for (int i = 0; i < TM; i++)
#pragma unroll
        for (int j = 0; j < TN; j++) c[i][j] = 0.f;

    // ---- skip GEMM: c += x[n0+., :] * W_skip[d0+., :]^T -------------------
    const int lr = tid >> 1;            // 0..127 (row within tile)
    const int lj = (tid & 1) * 4;       // 0 or 4 (j offset within JT)
    for (int j0 = 0; j0 < DIM; j0 += JT) {
        float4 xv = *(const float4*)&x[(size_t)(n0 + lr) * DIM + j0 + lj];
        float4 wv = *(const float4*)&W_skip[(size_t)(d0 + lr) * DIM + j0 + lj];
        __syncthreads();
        xs[lj + 0][lr] = xv.x; xs[lj + 1][lr] = xv.y;
        xs[lj + 2][lr] = xv.z; xs[lj + 3][lr] = xv.w;
        ws[lj + 0][lr] = wv.x; ws[lj + 1][lr] = wv.y;
        ws[lj + 2][lr] = wv.z; ws[lj + 3][lr] = wv.w;
        __syncthreads();
#pragma unroll
        for (int jj = 0; jj < JT; jj++) {
            float4 a0 = *(const float4*)&xs[jj][ty * 8];
            float4 a1 = *(const float4*)&xs[jj][ty * 8 + 4];
            float4 b0 = *(const float4*)&ws[jj][tx * 8];
            float4 b1 = *(const float4*)&ws[jj][tx * 8 + 4];
            float a[TM] = {a0.x, a0.y, a0.z, a0.w, a1.x, a1.y, a1.z, a1.w};
            float b[TN] = {b0.x, b0.y, b0.z, b0.w, b1.x, b1.y, b1.z, b1.w};
#pragma unroll
            for (int i = 0; i < TM; i++)
#pragma unroll
                for (int j = 0; j < TN; j++) c[i][j] += a[i] * b[j];
        }
    }

    // ---- sparse decode: c += acts[n,k] * W_dec[idx[n,k], d] ---------------
    for (int kh = 0; kh < 2; kh++) {
        __syncthreads();
        // stage 128 tokens x 32 k of (scaled acts, idx)
#pragma unroll
        for (int q = 0; q < 16; q++) {
            int e = tid * 16 + q;          // 0..4095
            int t = e >> 5;                // token 0..127
            int k = e & 31;
            int gi = (n0 + t) * KTOP + kh * 32 + k;
            int id = lat_idx[gi];
            acts_s[t][k] = (lat_acts[gi] + post_enc[id]) * post_enc_scale[id];
            idx_s[t][k] = id;
        }
        __syncthreads();
        for (int k = 0; k < 32; k++) {
#pragma unroll
            for (int i = 0; i < TM; i++) {
                int t = ty * 8 + i;
                int row = idx_s[t][k];
                float a = acts_s[t][k];
                const float4* wp =
                    (const float4*)&W_dec[(size_t)row * DIM + d0 + tx * 8];
                float4 w0 = wp[0];
                float4 w1 = wp[1];
                c[i][0] += a * w0.x; c[i][1] += a * w0.y;
                c[i][2] += a * w0.z; c[i][3] += a * w0.w;
                c[i][4] += a * w1.x; c[i][5] += a * w1.y;
                c[i][6] += a * w1.z; c[i][7] += a * w1.w;
            }
        }
    }

    // ---- epilogue: add b_dec, store, accumulate err -----------------------
    float err = 0.f;
#pragma unroll
    for (int i = 0; i < TM; i++) {
        int n = n0 + ty * 8 + i;
#pragma unroll
        for (int j = 0; j < TN; j += 4) {
            int d = d0 + tx * 8 + j;
            float4 bd = *(const float4*)&b_dec[d];
            float4 yv = *(const float4*)&y[(size_t)n * DIM + d];
            float4 o;
            o.x = c[i][j + 0] + bd.x;
            o.y = c[i][j + 1] + bd.y;
            o.z = c[i][j + 2] + bd.z;
            o.w = c[i][j + 3] + bd.w;
            *(float4*)&out[(size_t)n * DIM + d] = o;
            float e0 = yv.x - o.x, e1 = yv.y - o.y;
            float e2 = yv.z - o.z, e3 = yv.w - o.w;
            err += e0 * e0 + e1 * e1 + e2 * e2 + e3 * e3;
        }
    }

    red[tid] = err;
    __syncthreads();
    for (int st = 128; st > 0; st >>= 1) {
        if (tid < st) red[tid] += red[tid + st];
        __syncthreads();
    }
    if (tid == 0)
        g_err_part[blockIdx.y * gridDim.x + blockIdx.x] = red[0];
}

// ---------------------------------------------------------------------------
// Kernel C: finalize fvu = sum(e^2) / (sum(y^2) - sum_d colsum_d^2 / N)
// single block, 256 threads, fixed reduction order (deterministic)
// ---------------------------------------------------------------------------
__global__ void finalize_kernel(float* __restrict__ out, int fvu_idx)
{
    int tid = threadIdx.x;
    float csq = 0.f;
    for (int d = tid; d < DIM; d += 256) {
        float cs = 0.f;
#pragma unroll
        for (int r = 0; r < 32; r++) cs += g_colsum_part[r * DIM + d];
        csq += cs * cs;
    }
    float s2 = 0.f;
    for (int i = tid; i < 128; i += 256) s2 += g_s2_part[i];
    float err = 0.f;
    for (int i = tid; i < 256; i += 256) err += g_err_part[i];

    __shared__ float r1[256], r2[256], r3[256];
    r1[tid] = csq; r2[tid] = s2; r3[tid] = err;
    __syncthreads();
    for (int st = 128; st > 0; st >>= 1) {
        if (tid < st) {
            r1[tid] += r1[tid + st];
            r2[tid] += r2[tid + st];
            r3[tid] += r3[tid + st];
        }
        __syncthreads();
    }
    if (tid == 0) {
        float tv = r2[0] - r1[0] / (float)NTOK;
        out[fvu_idx] = r3[0] / tv;
    }
}

// ---------------------------------------------------------------------------
extern "C" void kernel_launch(void* const* d_in, const int* in_sizes, int n_in,
                              void* d_out, int out_size)
{
    const float* x        = (const float*)d_in[0];
    const float* y        = (const float*)d_in[1];
    const float* lat_acts = (const float*)d_in[2];
    const int*   lat_idx  = (const int*)  d_in[3];
    const float* W_dec    = (const float*)d_in[4];
    const float* b_dec    = (const float*)d_in[5];
    const float* post_enc = (const float*)d_in[6];
    const float* pes      = (const float*)d_in[7];
    const float* W_skip   = (const float*)d_in[8];
    float* out = (float*)d_out;

    // A: y column stats
    colstats_kernel<<<dim3(4, 32), 256>>>(y);

    // B: fused skip-GEMM + sparse decode + bias + err partials
    fused_kernel<<<dim3(DIM / BD, NTOK / BN), 256>>>(
        x, y, lat_acts, lat_idx, W_dec, b_dec, post_enc, pes, W_skip, out);

    // C: fvu scalar at the tail of the output buffer
    finalize_kernel<<<1, 256>>>(out, out_size - 1);
}

// round 4
// speedup vs baseline: 1.5435x; 1.5435x over previous
#include <cuda_runtime.h>
#include <cuda_bf16.h>
#include <cstdint>

#define NTOK 4096
#define KTOP 64
#define DIM  1024
#define NLAT 16384

// ---------------------------------------------------------------------------
// Static device scratch (no runtime allocations allowed)
// ---------------------------------------------------------------------------
__device__ __nv_bfloat16 g_Xh[NTOK * DIM];
__device__ __nv_bfloat16 g_Xl[NTOK * DIM];
__device__ __nv_bfloat16 g_Wh[DIM * DIM];
__device__ __nv_bfloat16 g_Wl[DIM * DIM];
__device__ __nv_bfloat16 g_Wdecb[NLAT * DIM];
__device__ float g_colsum_part[256 * DIM];
__device__ float g_s2_part[256 * 4];
__device__ float g_err_part[256];

// ---------------------------------------------------------------------------
// MMA / ldmatrix helpers (baseline PTX, works at compute_103 target)
// ---------------------------------------------------------------------------
__device__ __forceinline__ void mma16816(float* d, const uint32_t* a,
                                         const uint32_t* b) {
    asm volatile(
        "mma.sync.aligned.m16n8k16.row.col.f32.bf16.bf16.f32 "
        "{%0,%1,%2,%3}, {%4,%5,%6,%7}, {%8,%9}, {%0,%1,%2,%3};"
        : "+f"(d[0]), "+f"(d[1]), "+f"(d[2]), "+f"(d[3])
        : "r"(a[0]), "r"(a[1]), "r"(a[2]), "r"(a[3]), "r"(b[0]), "r"(b[1]));
}
__device__ __forceinline__ void ldsm4(uint32_t* r, uint32_t addr) {
    asm volatile("ldmatrix.sync.aligned.m8n8.x4.shared.b16 {%0,%1,%2,%3}, [%4];"
                 : "=r"(r[0]), "=r"(r[1]), "=r"(r[2]), "=r"(r[3]) : "r"(addr));
}
__device__ __forceinline__ void ldsm2(uint32_t* r, uint32_t addr) {
    asm volatile("ldmatrix.sync.aligned.m8n8.x2.shared.b16 {%0,%1}, [%2];"
                 : "=r"(r[0]), "=r"(r[1]) : "r"(addr));
}
__device__ __forceinline__ uint32_t smem_to_u32(const void* p) {
    uint32_t a;
    asm("{ .reg .u64 t; cvta.to.shared.u64 t, %1; cvt.u32.u64 %0, t; }"
        : "=r"(a) : "l"(p));
    return a;
}

// ---------------------------------------------------------------------------
// Convert kernel: X,W_skip -> bf16 hi/lo split; W_dec -> bf16
// ---------------------------------------------------------------------------
#define XU4  (NTOK * DIM / 4)
#define WU4  (DIM * DIM / 4)
#define WDU4 (NLAT * DIM / 4)

__device__ __forceinline__ void split4(const float4* src, int u,
                                       __nv_bfloat16* hi, __nv_bfloat16* lo) {
    float4 v = src[u];
    __nv_bfloat16 h0 = __float2bfloat16(v.x), h1 = __float2bfloat16(v.y);
    __nv_bfloat16 h2 = __float2bfloat16(v.z), h3 = __float2bfloat16(v.w);
    __nv_bfloat162* hp = (__nv_bfloat162*)(hi + 4 * (size_t)u);
    hp[0] = __nv_bfloat162(h0, h1);
    hp[1] = __nv_bfloat162(h2, h3);
    __nv_bfloat162* lp = (__nv_bfloat162*)(lo + 4 * (size_t)u);
    lp[0] = __nv_bfloat162(__float2bfloat16(v.x - __bfloat162float(h0)),
                           __float2bfloat16(v.y - __bfloat162float(h1)));
    lp[1] = __nv_bfloat162(__float2bfloat16(v.z - __bfloat162float(h2)),
                           __float2bfloat16(v.w - __bfloat162float(h3)));
}

__global__ void convert_kernel(const float* __restrict__ x,
                               const float* __restrict__ wskip,
                               const float* __restrict__ wdec) {
    int i = blockIdx.x * blockDim.x + threadIdx.x;
    int stride = gridDim.x * blockDim.x;
    const int total = XU4 + WU4 + WDU4;
    for (int u = i; u < total; u += stride) {
        if (u < XU4) {
            split4((const float4*)x, u, g_Xh, g_Xl);
        } else if (u < XU4 + WU4) {
            split4((const float4*)wskip, u - XU4, g_Wh, g_Wl);
        } else {
            int v = u - XU4 - WU4;
            float4 w = ((const float4*)wdec)[v];
            __nv_bfloat162* dp = (__nv_bfloat162*)(g_Wdecb + 4 * (size_t)v);
            dp[0] = __nv_bfloat162(__float2bfloat16(w.x), __float2bfloat16(w.y));
            dp[1] = __nv_bfloat162(__float2bfloat16(w.z), __float2bfloat16(w.w));
        }
    }
}

// ---------------------------------------------------------------------------
// colstats: per-column sums of y + partial sum(y^2). grid(4,256), 16 rows each.
// ---------------------------------------------------------------------------
__global__ void colstats_kernel(const float* __restrict__ y) {
    int d  = blockIdx.x * 256 + threadIdx.x;
    int r0 = blockIdx.y * 16;
    float s = 0.f, s2 = 0.f;
    const float* yp = y + (size_t)r0 * DIM + d;
#pragma unroll
    for (int r = 0; r < 16; r++) {
        float v = yp[(size_t)r * DIM];
        s += v; s2 += v * v;
    }
    g_colsum_part[blockIdx.y * DIM + d] = s;
    __shared__ float red[256];
    red[threadIdx.x] = s2;
    __syncthreads();
    for (int st = 128; st > 0; st >>= 1) {
        if (threadIdx.x < st) red[threadIdx.x] += red[threadIdx.x + st];
        __syncthreads();
    }
    if (threadIdx.x == 0) g_s2_part[blockIdx.y * 4 + blockIdx.x] = red[0];
}

// ---------------------------------------------------------------------------
// Fused: HMMA skip-GEMM (bf16 3-term split) + sparse decode + epilogue
// tile 128 tokens x 128 cols, grid (8, 32), 256 threads = 8 warps (2M x 4N)
// ---------------------------------------------------------------------------
#define LDA 72                     // bf16 per smem row (144 B, conflict-free)
#define TILEB (128 * LDA * 2)      // 18432 bytes per operand tile
#define SM_AH 0
#define SM_AL (1 * TILEB)
#define SM_BH (2 * TILEB)
#define SM_BL (3 * TILEB)          // GEMM region total 73728
#define EXLD 132                   // exchange row stride (floats)
#define SM_EX   0                  // 128*132*4 = 67584 (overlays GEMM region)
#define SM_ACTS 67584              // 16384
#define SM_IDX  (67584 + 16384)    // 16384
#define SM_RED  (67584 + 32768)    // 1024
#define SMEM_DYN (67584 + 32768 + 1024)   // 101376

__global__ void __launch_bounds__(256, 2)
fused_kernel(const float* __restrict__ y,
             const float* __restrict__ lat_acts,
             const int*   __restrict__ lat_idx,
             const float* __restrict__ b_dec,
             const float* __restrict__ post_enc,
             const float* __restrict__ pes,
             float* __restrict__ out)
{
    extern __shared__ char smem[];
    const uint32_t sb = smem_to_u32(smem);
    const int tid  = threadIdx.x;
    const int wid  = tid >> 5;
    const int lane = tid & 31;
    const int wm = wid & 1;        // 2 M-groups of 64 rows
    const int wn = wid >> 1;       // 4 N-groups of 32 cols
    const int tx = tid & 15;       // d group (decode/epilogue)
    const int ty = tid >> 4;       // token group
    const int n0 = blockIdx.y * 128;
    const int d0 = blockIdx.x * 128;

    // ---- GEMM phase: HMMA over 16 K-chunks of 64 ------------------------
    const __nv_bfloat16* gAh = g_Xh + (size_t)n0 * DIM;
    const __nv_bfloat16* gAl = g_Xl + (size_t)n0 * DIM;
    const __nv_bfloat16* gBh = g_Wh + (size_t)d0 * DIM;
    const __nv_bfloat16* gBl = g_Wl + (size_t)d0 * DIM;

    float acc[4][4][4];
#pragma unroll
    for (int i = 0; i < 4; i++)
#pragma unroll
        for (int j = 0; j < 4; j++)
#pragma unroll
            for (int e = 0; e < 4; e++) acc[i][j][e] = 0.f;

    // per-lane ldmatrix address offsets (bytes)
    const uint32_t aoff =
        (uint32_t)(((((lane >> 3) & 1) * 8 + (lane & 7)) * LDA + (lane >> 4) * 8) * 2);
    const uint32_t boff =
        (uint32_t)(((lane & 7) * LDA + ((lane >> 3) & 1) * 8) * 2);
    const uint32_t abase = sb + aoff + (uint32_t)(wm * 64 * LDA * 2);
    const uint32_t bbase = sb + boff + (uint32_t)(wn * 32 * LDA * 2);

    for (int kc = 0; kc < 16; kc++) {
        __syncthreads();
#pragma unroll
        for (int q = 0; q < 4; q++) {
            int u = q * 256 + tid;             // 0..1023
            int row = u >> 3, kq = u & 7;
            size_t go = (size_t)row * DIM + kc * 64 + kq * 8;
            uint32_t so = (uint32_t)((row * LDA + kq * 8) * 2);
            *(uint4*)(smem + SM_AH + so) = *(const uint4*)(gAh + go);
            *(uint4*)(smem + SM_AL + so) = *(const uint4*)(gAl + go);
            *(uint4*)(smem + SM_BH + so) = *(const uint4*)(gBh + go);
            *(uint4*)(smem + SM_BL + so) = *(const uint4*)(gBl + go);
        }
        __syncthreads();
#pragma unroll
        for (int ks = 0; ks < 4; ks++) {
            const uint32_t kb = ks * 32;       // byte offset of k-step (16 bf16)
            uint32_t bh[4][2], bl[4][2];
#pragma unroll
            for (int nf = 0; nf < 4; nf++) {
                uint32_t bo = bbase + (uint32_t)(nf * 8 * LDA * 2) + kb;
                ldsm2(bh[nf], bo + SM_BH);
                ldsm2(bl[nf], bo + SM_BL);
            }
#pragma unroll
            for (int mf = 0; mf < 4; mf++) {
                uint32_t ao = abase + (uint32_t)(mf * 16 * LDA * 2) + kb;
                uint32_t ah[4], al[4];
                ldsm4(ah, ao + SM_AH);
#pragma unroll
                for (int nf = 0; nf < 4; nf++) mma16816(acc[mf][nf], ah, bh[nf]);
#pragma unroll
                for (int nf = 0; nf < 4; nf++) mma16816(acc[mf][nf], ah, bl[nf]);
                ldsm4(al, ao + SM_AL);
#pragma unroll
                for (int nf = 0; nf < 4; nf++) mma16816(acc[mf][nf], al, bh[nf]);
            }
        }
    }

    // ---- spill accumulators to smem exchange buffer ---------------------
    __syncthreads();               // everyone done reading GEMM tiles
    float* ex = (float*)(smem + SM_EX);   // [128][EXLD]
    {
        int r0 = wm * 64 + (lane >> 2);
        int c0 = wn * 32 + 2 * (lane & 3);
#pragma unroll
        for (int mf = 0; mf < 4; mf++)
#pragma unroll
            for (int nf = 0; nf < 4; nf++) {
                int r = r0 + mf * 16, c = c0 + nf * 8;
                *(float2*)&ex[r * EXLD + c] =
                    make_float2(acc[mf][nf][0], acc[mf][nf][1]);
                *(float2*)&ex[(r + 8) * EXLD + c] =
                    make_float2(acc[mf][nf][2], acc[mf][nf][3]);
            }
    }

    // ---- decode phase: c += acts * W_dec[idx] ---------------------------
    float* acts_s = (float*)(smem + SM_ACTS);  // [128][32]
    int*   idx_s  = (int*)  (smem + SM_IDX);   // [128][32]
    float c[8][8];
#pragma unroll
    for (int i = 0; i < 8; i++)
#pragma unroll
        for (int j = 0; j < 8; j++) c[i][j] = 0.f;

    for (int kh = 0; kh < 2; kh++) {
        __syncthreads();
#pragma unroll
        for (int q = 0; q < 16; q++) {
            int e = tid * 16 + q;
            int t = e >> 5, k = e & 31;
            int gi = (n0 + t) * KTOP + kh * 32 + k;
            int id = lat_idx[gi];
            acts_s[t * 32 + k] = (lat_acts[gi] + post_enc[id]) * pes[id];
            idx_s[t * 32 + k] = id;
        }
        __syncthreads();
        for (int k = 0; k < 32; k++) {
#pragma unroll
            for (int i = 0; i < 8; i++) {
                int t = ty * 8 + i;
                int row = idx_s[t * 32 + k];
                float a = acts_s[t * 32 + k];
                uint4 u = *(const uint4*)(g_Wdecb + (size_t)row * DIM + d0 + tx * 8);
                __nv_bfloat162 b0 = *(__nv_bfloat162*)&u.x;
                __nv_bfloat162 b1 = *(__nv_bfloat162*)&u.y;
                __nv_bfloat162 b2 = *(__nv_bfloat162*)&u.z;
                __nv_bfloat162 b3 = *(__nv_bfloat162*)&u.w;
                float2 f0 = __bfloat1622float2(b0), f1 = __bfloat1622float2(b1);
                float2 f2 = __bfloat1622float2(b2), f3 = __bfloat1622float2(b3);
                c[i][0] += a * f0.x; c[i][1] += a * f0.y;
                c[i][2] += a * f1.x; c[i][3] += a * f1.y;
                c[i][4] += a * f2.x; c[i][5] += a * f2.y;
                c[i][6] += a * f3.x; c[i][7] += a * f3.y;
            }
        }
    }
    __syncthreads();

    // ---- combine: skip + decode + b_dec -> out, err partial -------------
    float err = 0.f;
#pragma unroll
    for (int i = 0; i < 8; i++) {
        int t = ty * 8 + i;
        int n = n0 + t;
#pragma unroll
        for (int j = 0; j < 8; j += 4) {
            int d = d0 + tx * 8 + j;
            float4 bd = *(const float4*)&b_dec[d];
            float4 yv = *(const float4*)&y[(size_t)n * DIM + d];
            float4 sv = *(const float4*)&ex[t * EXLD + tx * 8 + j];
            float4 o;
            o.x = c[i][j + 0] + sv.x + bd.x;
            o.y = c[i][j + 1] + sv.y + bd.y;
            o.z = c[i][j + 2] + sv.z + bd.z;
            o.w = c[i][j + 3] + sv.w + bd.w;
            *(float4*)&out[(size_t)n * DIM + d] = o;
            float e0 = yv.x - o.x, e1 = yv.y - o.y;
            float e2 = yv.z - o.z, e3 = yv.w - o.w;
            err += e0 * e0 + e1 * e1 + e2 * e2 + e3 * e3;
        }
    }

    float* red = (float*)(smem + SM_RED);
    red[tid] = err;
    __syncthreads();
    for (int st = 128; st > 0; st >>= 1) {
        if (tid < st) red[tid] += red[tid + st];
        __syncthreads();
    }
    if (tid == 0) g_err_part[blockIdx.y * gridDim.x + blockIdx.x] = red[0];
}

// ---------------------------------------------------------------------------
// finalize: fvu = sum(e^2) / (sum(y^2) - sum_d colsum_d^2 / N)
// ---------------------------------------------------------------------------
__global__ void finalize_kernel(float* __restrict__ out, int fvu_idx) {
    int tid = threadIdx.x;
    float csq = 0.f;
    for (int d = tid; d < DIM; d += 256) {
        float cs = 0.f;
#pragma unroll
        for (int r = 0; r < 256; r++) cs += g_colsum_part[r * DIM + d];
        csq += cs * cs;
    }
    float s2 = 0.f;
    for (int i = tid; i < 1024; i += 256) s2 += g_s2_part[i];
    float err = g_err_part[tid];

    __shared__ float r1[256], r2[256], r3[256];
    r1[tid] = csq; r2[tid] = s2; r3[tid] = err;
    __syncthreads();
    for (int st = 128; st > 0; st >>= 1) {
        if (tid < st) {
            r1[tid] += r1[tid + st];
            r2[tid] += r2[tid + st];
            r3[tid] += r3[tid + st];
        }
        __syncthreads();
    }
    if (tid == 0) {
        float tv = r2[0] - r1[0] / (float)NTOK;
        out[fvu_idx] = r3[0] / tv;
    }
}

// ---------------------------------------------------------------------------
extern "C" void kernel_launch(void* const* d_in, const int* in_sizes, int n_in,
                              void* d_out, int out_size)
{
    const float* x        = (const float*)d_in[0];
    const float* y        = (const float*)d_in[1];
    const float* lat_acts = (const float*)d_in[2];
    const int*   lat_idx  = (const int*)  d_in[3];
    const float* W_dec    = (const float*)d_in[4];
    const float* b_dec    = (const float*)d_in[5];
    const float* post_enc = (const float*)d_in[6];
    const float* pes      = (const float*)d_in[7];
    const float* W_skip   = (const float*)d_in[8];
    float* out = (float*)d_out;

    cudaFuncSetAttribute(fused_kernel,
                         cudaFuncAttributeMaxDynamicSharedMemorySize, SMEM_DYN);

    convert_kernel<<<1024, 256>>>(x, W_skip, W_dec);
    colstats_kernel<<<dim3(4, 256), 256>>>(y);
    fused_kernel<<<dim3(8, 32), 256, SMEM_DYN>>>(
        y, lat_acts, lat_idx, b_dec, post_enc, pes, out);
    finalize_kernel<<<1, 256>>>(out, out_size - 1);
}

// round 5
// speedup vs baseline: 1.7951x; 1.1630x over previous
#include <cuda_runtime.h>
#include <cuda_bf16.h>
#include <cstdint>

#define NTOK 4096
#define KTOP 64
#define DIM  1024
#define NLAT 16384

// ---------------------------------------------------------------------------
// Static device scratch (no runtime allocations allowed)
// ---------------------------------------------------------------------------
__device__ __nv_bfloat16 g_Xh[NTOK * DIM];
__device__ __nv_bfloat16 g_Xl[NTOK * DIM];
__device__ __nv_bfloat16 g_Wh[DIM * DIM];
__device__ __nv_bfloat16 g_Wl[DIM * DIM];
__device__ __nv_bfloat16 g_Wdecb[NLAT * DIM];
__device__ float g_colsum_part[256 * DIM];
__device__ float g_s2_part[256 * 4];
__device__ float g_err_part[256];

// ---------------------------------------------------------------------------
// MMA / ldmatrix / cp.async helpers (baseline PTX, safe at compute_103)
// ---------------------------------------------------------------------------
__device__ __forceinline__ void mma16816(float* d, const uint32_t* a,
                                         const uint32_t* b) {
    asm volatile(
        "mma.sync.aligned.m16n8k16.row.col.f32.bf16.bf16.f32 "
        "{%0,%1,%2,%3}, {%4,%5,%6,%7}, {%8,%9}, {%0,%1,%2,%3};"
        : "+f"(d[0]), "+f"(d[1]), "+f"(d[2]), "+f"(d[3])
        : "r"(a[0]), "r"(a[1]), "r"(a[2]), "r"(a[3]), "r"(b[0]), "r"(b[1]));
}
__device__ __forceinline__ void ldsm4(uint32_t* r, uint32_t addr) {
    asm volatile("ldmatrix.sync.aligned.m8n8.x4.shared.b16 {%0,%1,%2,%3}, [%4];"
                 : "=r"(r[0]), "=r"(r[1]), "=r"(r[2]), "=r"(r[3]) : "r"(addr));
}
__device__ __forceinline__ void ldsm2(uint32_t* r, uint32_t addr) {
    asm volatile("ldmatrix.sync.aligned.m8n8.x2.shared.b16 {%0,%1}, [%2];"
                 : "=r"(r[0]), "=r"(r[1]) : "r"(addr));
}
__device__ __forceinline__ uint32_t smem_to_u32(const void* p) {
    uint32_t a;
    asm("{ .reg .u64 t; cvta.to.shared.u64 t, %1; cvt.u32.u64 %0, t; }"
        : "=r"(a) : "l"(p));
    return a;
}
__device__ __forceinline__ void cp16(uint32_t dst, const void* src) {
    asm volatile("cp.async.cg.shared.global [%0], [%1], 16;"
                 :: "r"(dst), "l"(src) : "memory");
}
#define CP_COMMIT() asm volatile("cp.async.commit_group;" ::: "memory")
#define CP_WAIT1()  asm volatile("cp.async.wait_group 1;" ::: "memory")
#define CP_WAIT0()  asm volatile("cp.async.wait_group 0;" ::: "memory")

// ---------------------------------------------------------------------------
// Convert kernel: X,W_skip -> bf16 hi/lo split; W_dec -> bf16
// ---------------------------------------------------------------------------
#define XU4  (NTOK * DIM / 4)
#define WU4  (DIM * DIM / 4)
#define WDU4 (NLAT * DIM / 4)

__device__ __forceinline__ void split4(const float4* src, int u,
                                       __nv_bfloat16* hi, __nv_bfloat16* lo) {
    float4 v = src[u];
    __nv_bfloat16 h0 = __float2bfloat16(v.x), h1 = __float2bfloat16(v.y);
    __nv_bfloat16 h2 = __float2bfloat16(v.z), h3 = __float2bfloat16(v.w);
    __nv_bfloat162* hp = (__nv_bfloat162*)(hi + 4 * (size_t)u);
    hp[0] = __nv_bfloat162(h0, h1);
    hp[1] = __nv_bfloat162(h2, h3);
    __nv_bfloat162* lp = (__nv_bfloat162*)(lo + 4 * (size_t)u);
    lp[0] = __nv_bfloat162(__float2bfloat16(v.x - __bfloat162float(h0)),
                           __float2bfloat16(v.y - __bfloat162float(h1)));
    lp[1] = __nv_bfloat162(__float2bfloat16(v.z - __bfloat162float(h2)),
                           __float2bfloat16(v.w - __bfloat162float(h3)));
}

__global__ void convert_kernel(const float* __restrict__ x,
                               const float* __restrict__ wskip,
                               const float* __restrict__ wdec) {
    int i = blockIdx.x * blockDim.x + threadIdx.x;
    int stride = gridDim.x * blockDim.x;
    const int total = XU4 + WU4 + WDU4;
    for (int u = i; u < total; u += stride) {
        if (u < XU4) {
            split4((const float4*)x, u, g_Xh, g_Xl);
        } else if (u < XU4 + WU4) {
            split4((const float4*)wskip, u - XU4, g_Wh, g_Wl);
        } else {
            int v = u - XU4 - WU4;
            float4 w = ((const float4*)wdec)[v];
            __nv_bfloat162* dp = (__nv_bfloat162*)(g_Wdecb + 4 * (size_t)v);
            dp[0] = __nv_bfloat162(__float2bfloat16(w.x), __float2bfloat16(w.y));
            dp[1] = __nv_bfloat162(__float2bfloat16(w.z), __float2bfloat16(w.w));
        }
    }
}

// ---------------------------------------------------------------------------
// colstats: per-column sums of y + partial sum(y^2). grid(4,256), 16 rows each
// ---------------------------------------------------------------------------
__global__ void colstats_kernel(const float* __restrict__ y) {
    int d  = blockIdx.x * 256 + threadIdx.x;
    int r0 = blockIdx.y * 16;
    float s = 0.f, s2 = 0.f;
    const float* yp = y + (size_t)r0 * DIM + d;
#pragma unroll
    for (int r = 0; r < 16; r++) {
        float v = yp[(size_t)r * DIM];
        s += v; s2 += v * v;
    }
    g_colsum_part[blockIdx.y * DIM + d] = s;
    __shared__ float red[256];
    red[threadIdx.x] = s2;
    __syncthreads();
    for (int st = 128; st > 0; st >>= 1) {
        if (threadIdx.x < st) red[threadIdx.x] += red[threadIdx.x + st];
        __syncthreads();
    }
    if (threadIdx.x == 0) g_s2_part[blockIdx.y * 4 + blockIdx.x] = red[0];
}

// ---------------------------------------------------------------------------
// Fused: cp.async double-buffered HMMA skip-GEMM + sparse decode + epilogue
// tile 128 tokens x 128 cols, grid (8, 32), 256 threads = 8 warps (2M x 4N)
// K-chunk = 32, 2 stages
// ---------------------------------------------------------------------------
#define LDA 40                       // bf16 per smem row (80 B, conflict-free)
#define TILEB (128 * LDA * 2)        // 10240 bytes per operand tile
// buffer base: (stage*4 + tile) * TILEB ; tiles: 0=AH 1=AL 2=BH 3=BL
#define SM_GEMM_END (8 * TILEB)      // 81920
#define EXLD 132
#define SM_EX   0                    // 128*132*4 = 67584 (overlays stage bufs)
#define SM_ACTS 81920                // 128*16*4 = 8192
#define SM_IDX  (81920 + 8192)      // 8192
#define SM_RED  (81920 + 16384)     // 1024
#define SMEM_DYN (81920 + 16384 + 1024)   // 99328

__global__ void __launch_bounds__(256, 2)
fused_kernel(const float* __restrict__ y,
             const float* __restrict__ lat_acts,
             const int*   __restrict__ lat_idx,
             const float* __restrict__ b_dec,
             const float* __restrict__ post_enc,
             const float* __restrict__ pes,
             float* __restrict__ out)
{
    extern __shared__ char smem[];
    const uint32_t sb = smem_to_u32(smem);
    const int tid  = threadIdx.x;
    const int wid  = tid >> 5;
    const int lane = tid & 31;
    const int wm = wid & 1;          // 2 M-groups of 64 rows
    const int wn = wid >> 1;         // 4 N-groups of 32 cols
    const int tx = tid & 15;
    const int ty = tid >> 4;
    const int n0 = blockIdx.y * 128;
    const int d0 = blockIdx.x * 128;

    const __nv_bfloat16* gA[2] = {g_Xh + (size_t)n0 * DIM, g_Xl + (size_t)n0 * DIM};
    const __nv_bfloat16* gB[2] = {g_Wh + (size_t)d0 * DIM, g_Wl + (size_t)d0 * DIM};

    // per-thread load slot: 2 rows per operand tile (512 x 16B per tile)
    const int lrow = tid >> 1;              // 0..127
    const int lseg = (tid & 1) * 2;         // segments {0,1} or {2,3}

    // issue loads for chunk kc into stage st
    auto issue = [&](int kc, int st) {
        const uint32_t base = sb + (uint32_t)(st * 4 * TILEB);
        const size_t gof = (size_t)lrow * DIM + kc * 32 + lseg * 8;
        const uint32_t sof = (uint32_t)(lrow * (LDA * 2) + lseg * 16);
#pragma unroll
        for (int t = 0; t < 2; t++) {
            cp16(base + t * TILEB + sof,             gA[t] + gof);
            cp16(base + t * TILEB + sof + 16,        gA[t] + gof + 8);
            cp16(base + (2 + t) * TILEB + sof,       gB[t] + gof);
            cp16(base + (2 + t) * TILEB + sof + 16,  gB[t] + gof + 8);
        }
        CP_COMMIT();
    };

    float acc[4][4][4];
#pragma unroll
    for (int i = 0; i < 4; i++)
#pragma unroll
        for (int j = 0; j < 4; j++)
#pragma unroll
            for (int e = 0; e < 4; e++) acc[i][j][e] = 0.f;

    // per-lane ldmatrix address offsets (bytes)
    const uint32_t aoff =
        (uint32_t)(((((lane >> 3) & 1) * 8 + (lane & 7)) * LDA + (lane >> 4) * 8) * 2);
    const uint32_t boff =
        (uint32_t)(((lane & 7) * LDA + ((lane >> 3) & 1) * 8) * 2);
    const uint32_t abase = sb + aoff + (uint32_t)(wm * 64 * LDA * 2);
    const uint32_t bbase = sb + boff + (uint32_t)(wn * 32 * LDA * 2);

    issue(0, 0);
    for (int kc = 0; kc < 32; kc++) {
        const int st = kc & 1;
        if (kc < 31) { issue(kc + 1, st ^ 1); CP_WAIT1(); }
        else         { CP_WAIT0(); }
        __syncthreads();
        const uint32_t stb = (uint32_t)(st * 4 * TILEB);
#pragma unroll
        for (int ks = 0; ks < 2; ks++) {
            const uint32_t kb = ks * 32;
            uint32_t bh[4][2], bl[4][2];
#pragma unroll
            for (int nf = 0; nf < 4; nf++) {
                uint32_t bo = bbase + stb + (uint32_t)(nf * 8 * LDA * 2) + kb;
                ldsm2(bh[nf], bo + 2 * TILEB);
                ldsm2(bl[nf], bo + 3 * TILEB);
            }
#pragma unroll
            for (int mf = 0; mf < 4; mf++) {
                uint32_t ao = abase + stb + (uint32_t)(mf * 16 * LDA * 2) + kb;
                uint32_t ah[4], al[4];
                ldsm4(ah, ao);
#pragma unroll
                for (int nf = 0; nf < 4; nf++) mma16816(acc[mf][nf], ah, bh[nf]);
#pragma unroll
                for (int nf = 0; nf < 4; nf++) mma16816(acc[mf][nf], ah, bl[nf]);
                ldsm4(al, ao + TILEB);
#pragma unroll
                for (int nf = 0; nf < 4; nf++) mma16816(acc[mf][nf], al, bh[nf]);
            }
        }
        __syncthreads();
    }

    // ---- spill accumulators to smem exchange buffer ---------------------
    float* ex = (float*)(smem + SM_EX);   // [128][EXLD]
    {
        int r0 = wm * 64 + (lane >> 2);
        int c0 = wn * 32 + 2 * (lane & 3);
#pragma unroll
        for (int mf = 0; mf < 4; mf++)
#pragma unroll
            for (int nf = 0; nf < 4; nf++) {
                int r = r0 + mf * 16, c = c0 + nf * 8;
                *(float2*)&ex[r * EXLD + c] =
                    make_float2(acc[mf][nf][0], acc[mf][nf][1]);
                *(float2*)&ex[(r + 8) * EXLD + c] =
                    make_float2(acc[mf][nf][2], acc[mf][nf][3]);
            }
    }

    // ---- decode phase: c += acts * W_dec[idx], 4 phases of 16 k ---------
    float* acts_s = (float*)(smem + SM_ACTS);  // [128][16]
    int*   idx_s  = (int*)  (smem + SM_IDX);   // [128][16]
    float c[8][8];
#pragma unroll
    for (int i = 0; i < 8; i++)
#pragma unroll
        for (int j = 0; j < 8; j++) c[i][j] = 0.f;

    for (int ph = 0; ph < 4; ph++) {
        __syncthreads();
#pragma unroll
        for (int q = 0; q < 8; q++) {
            int e = tid * 8 + q;          // 0..2047
            int t = e >> 4, k = e & 15;
            int gi = (n0 + t) * KTOP + ph * 16 + k;
            int id = lat_idx[gi];
            acts_s[t * 16 + k] = (lat_acts[gi] + post_enc[id]) * pes[id];
            idx_s[t * 16 + k] = id;
        }
        __syncthreads();
        for (int k = 0; k < 16; k++) {
#pragma unroll
            for (int i = 0; i < 8; i++) {
                int t = ty * 8 + i;
                int row = idx_s[t * 16 + k];
                float a = acts_s[t * 16 + k];
                uint4 u = *(const uint4*)(g_Wdecb + (size_t)row * DIM + d0 + tx * 8);
                __nv_bfloat162 b0 = *(__nv_bfloat162*)&u.x;
                __nv_bfloat162 b1 = *(__nv_bfloat162*)&u.y;
                __nv_bfloat162 b2 = *(__nv_bfloat162*)&u.z;
                __nv_bfloat162 b3 = *(__nv_bfloat162*)&u.w;
                float2 f0 = __bfloat1622float2(b0), f1 = __bfloat1622float2(b1);
                float2 f2 = __bfloat1622float2(b2), f3 = __bfloat1622float2(b3);
                c[i][0] += a * f0.x; c[i][1] += a * f0.y;
                c[i][2] += a * f1.x; c[i][3] += a * f1.y;
                c[i][4] += a * f2.x; c[i][5] += a * f2.y;
                c[i][6] += a * f3.x; c[i][7] += a * f3.y;
            }
        }
    }
    __syncthreads();

    // ---- combine: skip + decode + b_dec -> out, err partial -------------
    float err = 0.f;
#pragma unroll
    for (int i = 0; i < 8; i++) {
        int t = ty * 8 + i;
        int n = n0 + t;
#pragma unroll
        for (int j = 0; j < 8; j += 4) {
            int d = d0 + tx * 8 + j;
            float4 bd = *(const float4*)&b_dec[d];
            float4 yv = *(const float4*)&y[(size_t)n * DIM + d];
            float4 sv = *(const float4*)&ex[t * EXLD + tx * 8 + j];
            float4 o;
            o.x = c[i][j + 0] + sv.x + bd.x;
            o.y = c[i][j + 1] + sv.y + bd.y;
            o.z = c[i][j + 2] + sv.z + bd.z;
            o.w = c[i][j + 3] + sv.w + bd.w;
            *(float4*)&out[(size_t)n * DIM + d] = o;
            float e0 = yv.x - o.x, e1 = yv.y - o.y;
            float e2 = yv.z - o.z, e3 = yv.w - o.w;
            err += e0 * e0 + e1 * e1 + e2 * e2 + e3 * e3;
        }
    }

    float* red = (float*)(smem + SM_RED);
    red[tid] = err;
    __syncthreads();
    for (int st = 128; st > 0; st >>= 1) {
        if (tid < st) red[tid] += red[tid + st];
        __syncthreads();
    }
    if (tid == 0) g_err_part[blockIdx.y * gridDim.x + blockIdx.x] = red[0];
}

// ---------------------------------------------------------------------------
// finalize: 1024 threads, one y-column per thread (coalesced), then reduce
// fvu = sum(e^2) / (sum(y^2) - sum_d colsum_d^2 / N)
// ---------------------------------------------------------------------------
__global__ void finalize_kernel(float* __restrict__ out, int fvu_idx) {
    int tid = threadIdx.x;          // 0..1023
    float cs = 0.f;
#pragma unroll 8
    for (int r = 0; r < 256; r++) cs += g_colsum_part[r * DIM + tid];
    float csq = cs * cs;
    float s2 = g_s2_part[tid];
    float err = (tid < 256) ? g_err_part[tid] : 0.f;

    __shared__ float r1[1024], r2[1024], r3[1024];
    r1[tid] = csq; r2[tid] = s2; r3[tid] = err;
    __syncthreads();
    for (int st = 512; st > 0; st >>= 1) {
        if (tid < st) {
            r1[tid] += r1[tid + st];
            r2[tid] += r2[tid + st];
            r3[tid] += r3[tid + st];
        }
        __syncthreads();
    }
    if (tid == 0) {
        float tv = r2[0] - r1[0] / (float)NTOK;
        out[fvu_idx] = r3[0] / tv;
    }
}

// ---------------------------------------------------------------------------
extern "C" void kernel_launch(void* const* d_in, const int* in_sizes, int n_in,
                              void* d_out, int out_size)
{
    const float* x        = (const float*)d_in[0];
    const float* y        = (const float*)d_in[1];
    const float* lat_acts = (const float*)d_in[2];
    const int*   lat_idx  = (const int*)  d_in[3];
    const float* W_dec    = (const float*)d_in[4];
    const float* b_dec    = (const float*)d_in[5];
    const float* post_enc = (const float*)d_in[6];
    const float* pes      = (const float*)d_in[7];
    const float* W_skip   = (const float*)d_in[8];
    float* out = (float*)d_out;

    cudaFuncSetAttribute(fused_kernel,
                         cudaFuncAttributeMaxDynamicSharedMemorySize, SMEM_DYN);

    convert_kernel<<<1024, 256>>>(x, W_skip, W_dec);
    colstats_kernel<<<dim3(4, 256), 256>>>(y);
    fused_kernel<<<dim3(8, 32), 256, SMEM_DYN>>>(
        y, lat_acts, lat_idx, b_dec, post_enc, pes, out);
    finalize_kernel<<<1, 1024>>>(out, out_size - 1);
}

// round 6
// speedup vs baseline: 2.0200x; 1.1253x over previous
#include <cuda_runtime.h>
#include <cuda_bf16.h>
#include <cstdint>

#define NTOK 4096
#define KTOP 64
#define DIM  1024
#define NLAT 16384

// ---------------------------------------------------------------------------
// Static device scratch (no runtime allocations allowed)
// ---------------------------------------------------------------------------
__device__ __nv_bfloat16 g_Xh[NTOK * DIM];
__device__ __nv_bfloat16 g_Xl[NTOK * DIM];
__device__ __nv_bfloat16 g_Wh[DIM * DIM];
__device__ __nv_bfloat16 g_Wl[DIM * DIM];
__device__ __nv_bfloat16 g_Wdecb[NLAT * DIM];
__device__ float g_colsum_part[256 * DIM];
__device__ float g_colsum[DIM];
__device__ float g_s2_part[256 * 4];
__device__ float g_err_part[256];

// ---------------------------------------------------------------------------
// MMA / ldmatrix / cp.async helpers (baseline PTX, safe at compute_103)
// ---------------------------------------------------------------------------
__device__ __forceinline__ void mma16816(float* d, const uint32_t* a,
                                         const uint32_t* b) {
    asm volatile(
        "mma.sync.aligned.m16n8k16.row.col.f32.bf16.bf16.f32 "
        "{%0,%1,%2,%3}, {%4,%5,%6,%7}, {%8,%9}, {%0,%1,%2,%3};"
        : "+f"(d[0]), "+f"(d[1]), "+f"(d[2]), "+f"(d[3])
        : "r"(a[0]), "r"(a[1]), "r"(a[2]), "r"(a[3]), "r"(b[0]), "r"(b[1]));
}
__device__ __forceinline__ void ldsm4(uint32_t* r, uint32_t addr) {
    asm volatile("ldmatrix.sync.aligned.m8n8.x4.shared.b16 {%0,%1,%2,%3}, [%4];"
                 : "=r"(r[0]), "=r"(r[1]), "=r"(r[2]), "=r"(r[3]) : "r"(addr));
}
__device__ __forceinline__ void ldsm2(uint32_t* r, uint32_t addr) {
    asm volatile("ldmatrix.sync.aligned.m8n8.x2.shared.b16 {%0,%1}, [%2];"
                 : "=r"(r[0]), "=r"(r[1]) : "r"(addr));
}
__device__ __forceinline__ uint32_t smem_to_u32(const void* p) {
    uint32_t a;
    asm("{ .reg .u64 t; cvta.to.shared.u64 t, %1; cvt.u32.u64 %0, t; }"
        : "=r"(a) : "l"(p));
    return a;
}
__device__ __forceinline__ void cp16(uint32_t dst, const void* src) {
    asm volatile("cp.async.cg.shared.global [%0], [%1], 16;"
                 :: "r"(dst), "l"(src) : "memory");
}
#define CP_COMMIT() asm volatile("cp.async.commit_group;" ::: "memory")
#define CP_WAIT1()  asm volatile("cp.async.wait_group 1;" ::: "memory")
#define CP_WAIT0()  asm volatile("cp.async.wait_group 0;" ::: "memory")
#define NBAR(id, cnt) \
    asm volatile("bar.sync %0, %1;" :: "r"(id), "r"(cnt) : "memory")

// ---------------------------------------------------------------------------
// Convert kernel: X,W_skip -> bf16 hi/lo split; W_dec -> bf16
// ---------------------------------------------------------------------------
#define XU4  (NTOK * DIM / 4)
#define WU4  (DIM * DIM / 4)
#define WDU4 (NLAT * DIM / 4)

__device__ __forceinline__ void split4(const float4* src, int u,
                                       __nv_bfloat16* hi, __nv_bfloat16* lo) {
    float4 v = src[u];
    __nv_bfloat16 h0 = __float2bfloat16(v.x), h1 = __float2bfloat16(v.y);
    __nv_bfloat16 h2 = __float2bfloat16(v.z), h3 = __float2bfloat16(v.w);
    __nv_bfloat162* hp = (__nv_bfloat162*)(hi + 4 * (size_t)u);
    hp[0] = __nv_bfloat162(h0, h1);
    hp[1] = __nv_bfloat162(h2, h3);
    __nv_bfloat162* lp = (__nv_bfloat162*)(lo + 4 * (size_t)u);
    lp[0] = __nv_bfloat162(__float2bfloat16(v.x - __bfloat162float(h0)),
                           __float2bfloat16(v.y - __bfloat162float(h1)));
    lp[1] = __nv_bfloat162(__float2bfloat16(v.z - __bfloat162float(h2)),
                           __float2bfloat16(v.w - __bfloat162float(h3)));
}

__global__ void convert_kernel(const float* __restrict__ x,
                               const float* __restrict__ wskip,
                               const float* __restrict__ wdec) {
    int i = blockIdx.x * blockDim.x + threadIdx.x;
    int stride = gridDim.x * blockDim.x;
    const int total = XU4 + WU4 + WDU4;
    for (int u = i; u < total; u += stride) {
        if (u < XU4) {
            split4((const float4*)x, u, g_Xh, g_Xl);
        } else if (u < XU4 + WU4) {
            split4((const float4*)wskip, u - XU4, g_Wh, g_Wl);
        } else {
            int v = u - XU4 - WU4;
            float4 w = ((const float4*)wdec)[v];
            __nv_bfloat162* dp = (__nv_bfloat162*)(g_Wdecb + 4 * (size_t)v);
            dp[0] = __nv_bfloat162(__float2bfloat16(w.x), __float2bfloat16(w.y));
            dp[1] = __nv_bfloat162(__float2bfloat16(w.z), __float2bfloat16(w.w));
        }
    }
}

// ---------------------------------------------------------------------------
// colstats: per-column sums of y + partial sum(y^2). grid(4,256), 16 rows each
// ---------------------------------------------------------------------------
__global__ void colstats_kernel(const float* __restrict__ y) {
    int d  = blockIdx.x * 256 + threadIdx.x;
    int r0 = blockIdx.y * 16;
    float s = 0.f, s2 = 0.f;
    const float* yp = y + (size_t)r0 * DIM + d;
#pragma unroll
    for (int r = 0; r < 16; r++) {
        float v = yp[(size_t)r * DIM];
        s += v; s2 += v * v;
    }
    g_colsum_part[blockIdx.y * DIM + d] = s;
    __shared__ float red[256];
    red[threadIdx.x] = s2;
    __syncthreads();
    for (int st = 128; st > 0; st >>= 1) {
        if (threadIdx.x < st) red[threadIdx.x] += red[threadIdx.x + st];
        __syncthreads();
    }
    if (threadIdx.x == 0) g_s2_part[blockIdx.y * 4 + blockIdx.x] = red[0];
}

// ---------------------------------------------------------------------------
// reduce_colsum: collapse 256 row-partials -> g_colsum[1024]. grid 32 x 256.
// block b: columns b*32..b*32+31; thread (seg=t>>5, lane=t&31) sums 32 rows.
// ---------------------------------------------------------------------------
__global__ void reduce_colsum_kernel() {
    int t = threadIdx.x;
    int lane = t & 31, seg = t >> 5;          // 8 segs of 32 rows
    int col = blockIdx.x * 32 + lane;
    float s = 0.f;
#pragma unroll
    for (int r = 0; r < 32; r++)
        s += g_colsum_part[(seg * 32 + r) * DIM + col];
    __shared__ float sm[8][32];
    sm[seg][lane] = s;
    __syncthreads();
    if (seg == 0) {
        float v = sm[0][lane];
#pragma unroll
        for (int q = 1; q < 8; q++) v += sm[q][lane];
        g_colsum[col] = v;
    }
}

// ---------------------------------------------------------------------------
// Fused (warp-specialized): warps 0-7 = cp.async HMMA skip-GEMM,
// warps 8-15 = sparse decode. Join, then decode warps do the epilogue.
// tile 128 x 128, grid (8, 32), 512 threads.
// ---------------------------------------------------------------------------
#define LDA 40                       // bf16 per smem row (80 B, conflict-free)
#define TILEB (128 * LDA * 2)        // 10240 bytes per operand tile
#define EXLD 132
#define SM_EX   0                    // 128*132*4 = 67584 (overlays stage bufs)
#define SM_ACTS 81920                // 8192
#define SM_IDX  (81920 + 8192)       // 8192
#define SM_RED  (81920 + 16384)      // 1024 (256 floats)
#define SMEM_DYN (81920 + 16384 + 1024)

__global__ void __launch_bounds__(512, 1)
fused_kernel(const float* __restrict__ y,
             const float* __restrict__ lat_acts,
             const int*   __restrict__ lat_idx,
             const float* __restrict__ b_dec,
             const float* __restrict__ post_enc,
             const float* __restrict__ pes,
             float* __restrict__ out)
{
    extern __shared__ char smem[];
    const uint32_t sb = smem_to_u32(smem);
    const int tid  = threadIdx.x;
    const int n0 = blockIdx.y * 128;
    const int d0 = blockIdx.x * 128;

    if (tid < 256) {
        // ================= GEMM group (warps 0-7) =========================
        const int wid  = tid >> 5;
        const int lane = tid & 31;
        const int wm = wid & 1;          // 2 M-groups of 64 rows
        const int wn = wid >> 1;         // 4 N-groups of 32 cols

        const __nv_bfloat16* gA[2] = {g_Xh + (size_t)n0 * DIM,
                                      g_Xl + (size_t)n0 * DIM};
        const __nv_bfloat16* gB[2] = {g_Wh + (size_t)d0 * DIM,
                                      g_Wl + (size_t)d0 * DIM};
        const int lrow = tid >> 1;
        const int lseg = (tid & 1) * 2;

        auto issue = [&](int kc, int st) {
            const uint32_t base = sb + (uint32_t)(st * 4 * TILEB);
            const size_t gof = (size_t)lrow * DIM + kc * 32 + lseg * 8;
            const uint32_t sof = (uint32_t)(lrow * (LDA * 2) + lseg * 16);
#pragma unroll
            for (int t = 0; t < 2; t++) {
                cp16(base + t * TILEB + sof,            gA[t] + gof);
                cp16(base + t * TILEB + sof + 16,       gA[t] + gof + 8);
                cp16(base + (2 + t) * TILEB + sof,      gB[t] + gof);
                cp16(base + (2 + t) * TILEB + sof + 16, gB[t] + gof + 8);
            }
            CP_COMMIT();
        };

        float acc[4][4][4];
#pragma unroll
        for (int i = 0; i < 4; i++)
#pragma unroll
            for (int j = 0; j < 4; j++)
#pragma unroll
                for (int e = 0; e < 4; e++) acc[i][j][e] = 0.f;

        const uint32_t aoff = (uint32_t)(((((lane >> 3) & 1) * 8 + (lane & 7)) * LDA
                                          + (lane >> 4) * 8) * 2);
        const uint32_t boff = (uint32_t)(((lane & 7) * LDA + ((lane >> 3) & 1) * 8) * 2);
        const uint32_t abase = sb + aoff + (uint32_t)(wm * 64 * LDA * 2);
        const uint32_t bbase = sb + boff + (uint32_t)(wn * 32 * LDA * 2);

        issue(0, 0);
        for (int kc = 0; kc < 32; kc++) {
            const int st = kc & 1;
            if (kc < 31) { issue(kc + 1, st ^ 1); CP_WAIT1(); }
            else         { CP_WAIT0(); }
            NBAR(1, 256);
            const uint32_t stb = (uint32_t)(st * 4 * TILEB);
#pragma unroll
            for (int ks = 0; ks < 2; ks++) {
                const uint32_t kb = ks * 32;
                uint32_t bh[4][2], bl[4][2];
#pragma unroll
                for (int nf = 0; nf < 4; nf++) {
                    uint32_t bo = bbase + stb + (uint32_t)(nf * 8 * LDA * 2) + kb;
                    ldsm2(bh[nf], bo + 2 * TILEB);
                    ldsm2(bl[nf], bo + 3 * TILEB);
                }
#pragma unroll
                for (int mf = 0; mf < 4; mf++) {
                    uint32_t ao = abase + stb + (uint32_t)(mf * 16 * LDA * 2) + kb;
                    uint32_t ah[4], al[4];
                    ldsm4(ah, ao);
#pragma unroll
                    for (int nf = 0; nf < 4; nf++) mma16816(acc[mf][nf], ah, bh[nf]);
#pragma unroll
                    for (int nf = 0; nf < 4; nf++) mma16816(acc[mf][nf], ah, bl[nf]);
                    ldsm4(al, ao + TILEB);
#pragma unroll
                    for (int nf = 0; nf < 4; nf++) mma16816(acc[mf][nf], al, bh[nf]);
                }
            }
            NBAR(1, 256);
        }

        // spill accumulators to smem exchange buffer (overlays stage bufs)
        float* ex = (float*)(smem + SM_EX);
        int r0 = wm * 64 + (lane >> 2);
        int c0 = wn * 32 + 2 * (lane & 3);
#pragma unroll
        for (int mf = 0; mf < 4; mf++)
#pragma unroll
            for (int nf = 0; nf < 4; nf++) {
                int r = r0 + mf * 16, c = c0 + nf * 8;
                *(float2*)&ex[r * EXLD + c] =
                    make_float2(acc[mf][nf][0], acc[mf][nf][1]);
                *(float2*)&ex[(r + 8) * EXLD + c] =
                    make_float2(acc[mf][nf][2], acc[mf][nf][3]);
            }
        __syncthreads();   // join with decode group; GEMM warps done
    } else {
        // ================= Decode group (warps 8-15) ======================
        const int dtid = tid - 256;
        const int tx = dtid & 15;
        const int ty = dtid >> 4;
        float* acts_s = (float*)(smem + SM_ACTS);  // [128][16]
        int*   idx_s  = (int*)  (smem + SM_IDX);   // [128][16]
        float c[8][8];
#pragma unroll
        for (int i = 0; i < 8; i++)
#pragma unroll
            for (int j = 0; j < 8; j++) c[i][j] = 0.f;

        for (int ph = 0; ph < 4; ph++) {
            if (ph > 0) NBAR(2, 256);
#pragma unroll
            for (int q = 0; q < 8; q++) {
                int e = dtid * 8 + q;
                int t = e >> 4, k = e & 15;
                int gi = (n0 + t) * KTOP + ph * 16 + k;
                int id = lat_idx[gi];
                acts_s[t * 16 + k] = (lat_acts[gi] + post_enc[id]) * pes[id];
                idx_s[t * 16 + k] = id;
            }
            NBAR(2, 256);
            for (int k = 0; k < 16; k++) {
#pragma unroll
                for (int i = 0; i < 8; i++) {
                    int t = ty * 8 + i;
                    int row = idx_s[t * 16 + k];
                    float a = acts_s[t * 16 + k];
                    uint4 u = *(const uint4*)(g_Wdecb + (size_t)row * DIM + d0 + tx * 8);
                    __nv_bfloat162 b0 = *(__nv_bfloat162*)&u.x;
                    __nv_bfloat162 b1 = *(__nv_bfloat162*)&u.y;
                    __nv_bfloat162 b2 = *(__nv_bfloat162*)&u.z;
                    __nv_bfloat162 b3 = *(__nv_bfloat162*)&u.w;
                    float2 f0 = __bfloat1622float2(b0), f1 = __bfloat1622float2(b1);
                    float2 f2 = __bfloat1622float2(b2), f3 = __bfloat1622float2(b3);
                    c[i][0] += a * f0.x; c[i][1] += a * f0.y;
                    c[i][2] += a * f1.x; c[i][3] += a * f1.y;
                    c[i][4] += a * f2.x; c[i][5] += a * f2.y;
                    c[i][6] += a * f3.x; c[i][7] += a * f3.y;
                }
            }
        }
        __syncthreads();   // join: GEMM results now in ex

        // ---- epilogue: skip + decode + b_dec -> out, err partial --------
        float* ex = (float*)(smem + SM_EX);
        float err = 0.f;
#pragma unroll
        for (int i = 0; i < 8; i++) {
            int t = ty * 8 + i;
            int n = n0 + t;
#pragma unroll
            for (int j = 0; j < 8; j += 4) {
                int d = d0 + tx * 8 + j;
                float4 bd = *(const float4*)&b_dec[d];
                float4 yv = *(const float4*)&y[(size_t)n * DIM + d];
                float4 sv = *(const float4*)&ex[t * EXLD + tx * 8 + j];
                float4 o;
                o.x = c[i][j + 0] + sv.x + bd.x;
                o.y = c[i][j + 1] + sv.y + bd.y;
                o.z = c[i][j + 2] + sv.z + bd.z;
                o.w = c[i][j + 3] + sv.w + bd.w;
                *(float4*)&out[(size_t)n * DIM + d] = o;
                float e0 = yv.x - o.x, e1 = yv.y - o.y;
                float e2 = yv.z - o.z, e3 = yv.w - o.w;
                err += e0 * e0 + e1 * e1 + e2 * e2 + e3 * e3;
            }
        }

        float* red = (float*)(smem + SM_RED);
        red[dtid] = err;
        NBAR(2, 256);
        for (int st = 128; st > 0; st >>= 1) {
            if (dtid < st) red[dtid] += red[dtid + st];
            NBAR(2, 256);
        }
        if (dtid == 0) g_err_part[blockIdx.y * gridDim.x + blockIdx.x] = red[0];
    }
}

// ---------------------------------------------------------------------------
// finalize: tiny now. fvu = sum(e^2) / (sum(y^2) - sum_d colsum_d^2 / N)
// ---------------------------------------------------------------------------
__global__ void finalize_kernel(float* __restrict__ out, int fvu_idx) {
    int tid = threadIdx.x;          // 0..1023
    float cs = g_colsum[tid];
    float csq = cs * cs;
    float s2 = g_s2_part[tid];
    float err = (tid < 256) ? g_err_part[tid] : 0.f;

    __shared__ float r1[1024], r2[1024], r3[1024];
    r1[tid] = csq; r2[tid] = s2; r3[tid] = err;
    __syncthreads();
    for (int st = 512; st > 0; st >>= 1) {
        if (tid < st) {
            r1[tid] += r1[tid + st];
            r2[tid] += r2[tid + st];
            r3[tid] += r3[tid + st];
        }
        __syncthreads();
    }
    if (tid == 0) {
        float tv = r2[0] - r1[0] / (float)NTOK;
        out[fvu_idx] = r3[0] / tv;
    }
}

// ---------------------------------------------------------------------------
extern "C" void kernel_launch(void* const* d_in, const int* in_sizes, int n_in,
                              void* d_out, int out_size)
{
    const float* x        = (const float*)d_in[0];
    const float* y        = (const float*)d_in[1];
    const float* lat_acts = (const float*)d_in[2];
    const int*   lat_idx  = (const int*)  d_in[3];
    const float* W_dec    = (const float*)d_in[4];
    const float* b_dec    = (const float*)d_in[5];
    const float* post_enc = (const float*)d_in[6];
    const float* pes      = (const float*)d_in[7];
    const float* W_skip   = (const float*)d_in[8];
    float* out = (float*)d_out;

    cudaFuncSetAttribute(fused_kernel,
                         cudaFuncAttributeMaxDynamicSharedMemorySize, SMEM_DYN);

    convert_kernel<<<1024, 256>>>(x, W_skip, W_dec);
    colstats_kernel<<<dim3(4, 256), 256>>>(y);
    reduce_colsum_kernel<<<32, 256>>>();
    fused_kernel<<<dim3(8, 32), 512, SMEM_DYN>>>(
        y, lat_acts, lat_idx, b_dec, post_enc, pes, out);
    finalize_kernel<<<1, 1024>>>(out, out_size - 1);
}

// round 7
// speedup vs baseline: 2.0752x; 1.0273x over previous
#include <cuda_runtime.h>
#include <cuda_bf16.h>
#include <cstdint>

#define NTOK 4096
#define KTOP 64
#define DIM  1024
#define NLAT 16384

// ---------------------------------------------------------------------------
// Static device scratch (no runtime allocations allowed)
// ---------------------------------------------------------------------------
__device__ __nv_bfloat16 g_Xh[NTOK * DIM];
__device__ __nv_bfloat16 g_Xl[NTOK * DIM];
__device__ __nv_bfloat16 g_Wh[DIM * DIM];
__device__ __nv_bfloat16 g_Wl[DIM * DIM];
__device__ __nv_bfloat16 g_Wdecb[NLAT * DIM];
__device__ float g_colsum_part[256 * DIM];
__device__ float g_colsum[DIM];
__device__ float g_s2_part[256 * 4];
__device__ float g_err_part[256];

// ---------------------------------------------------------------------------
// MMA / ldmatrix / cp.async helpers (baseline PTX, safe at compute_103)
// ---------------------------------------------------------------------------
__device__ __forceinline__ void mma16816(float* d, const uint32_t* a,
                                         const uint32_t* b) {
    asm volatile(
        "mma.sync.aligned.m16n8k16.row.col.f32.bf16.bf16.f32 "
        "{%0,%1,%2,%3}, {%4,%5,%6,%7}, {%8,%9}, {%0,%1,%2,%3};"
        : "+f"(d[0]), "+f"(d[1]), "+f"(d[2]), "+f"(d[3])
        : "r"(a[0]), "r"(a[1]), "r"(a[2]), "r"(a[3]), "r"(b[0]), "r"(b[1]));
}
__device__ __forceinline__ void ldsm4(uint32_t* r, uint32_t addr) {
    asm volatile("ldmatrix.sync.aligned.m8n8.x4.shared.b16 {%0,%1,%2,%3}, [%4];"
                 : "=r"(r[0]), "=r"(r[1]), "=r"(r[2]), "=r"(r[3]) : "r"(addr));
}
__device__ __forceinline__ void ldsm2(uint32_t* r, uint32_t addr) {
    asm volatile("ldmatrix.sync.aligned.m8n8.x2.shared.b16 {%0,%1}, [%2];"
                 : "=r"(r[0]), "=r"(r[1]) : "r"(addr));
}
__device__ __forceinline__ uint32_t smem_to_u32(const void* p) {
    uint32_t a;
    asm("{ .reg .u64 t; cvta.to.shared.u64 t, %1; cvt.u32.u64 %0, t; }"
        : "=r"(a) : "l"(p));
    return a;
}
__device__ __forceinline__ void cp16(uint32_t dst, const void* src) {
    asm volatile("cp.async.cg.shared.global [%0], [%1], 16;"
                 :: "r"(dst), "l"(src) : "memory");
}
#define CP_COMMIT() asm volatile("cp.async.commit_group;" ::: "memory")
#define CP_WAIT3()  asm volatile("cp.async.wait_group 3;" ::: "memory")
#define CP_WAIT0()  asm volatile("cp.async.wait_group 0;" ::: "memory")
#define NBAR(id, cnt) \
    asm volatile("bar.sync %0, %1;" :: "r"(id), "r"(cnt) : "memory")

// ---------------------------------------------------------------------------
// prep: blocks 0-1023 = colstats (y column sums + y^2 partials),
//       blocks 1024-2047 = grid-stride convert (X,W_skip hi/lo; W_dec bf16)
// ---------------------------------------------------------------------------
#define XU4  (NTOK * DIM / 4)
#define WU4  (DIM * DIM / 4)
#define WDU4 (NLAT * DIM / 4)

__device__ __forceinline__ void split4(const float4* src, int u,
                                       __nv_bfloat16* hi, __nv_bfloat16* lo) {
    float4 v = src[u];
    __nv_bfloat16 h0 = __float2bfloat16(v.x), h1 = __float2bfloat16(v.y);
    __nv_bfloat16 h2 = __float2bfloat16(v.z), h3 = __float2bfloat16(v.w);
    __nv_bfloat162* hp = (__nv_bfloat162*)(hi + 4 * (size_t)u);
    hp[0] = __nv_bfloat162(h0, h1);
    hp[1] = __nv_bfloat162(h2, h3);
    __nv_bfloat162* lp = (__nv_bfloat162*)(lo + 4 * (size_t)u);
    lp[0] = __nv_bfloat162(__float2bfloat16(v.x - __bfloat162float(h0)),
                           __float2bfloat16(v.y - __bfloat162float(h1)));
    lp[1] = __nv_bfloat162(__float2bfloat16(v.z - __bfloat162float(h2)),
                           __float2bfloat16(v.w - __bfloat162float(h3)));
}

__global__ void prep_kernel(const float* __restrict__ x,
                            const float* __restrict__ y,
                            const float* __restrict__ wskip,
                            const float* __restrict__ wdec) {
    int b = blockIdx.x;
    if (b < 1024) {
        // ---- colstats: block (bx=b&3, by=b>>2): 256 cols x 16 rows ------
        int bx = b & 3, by = b >> 2;
        int d  = bx * 256 + threadIdx.x;
        const float* yp = y + (size_t)(by * 16) * DIM + d;
        float s = 0.f, s2 = 0.f;
#pragma unroll
        for (int r = 0; r < 16; r++) {
            float v = yp[(size_t)r * DIM];
            s += v; s2 += v * v;
        }
        g_colsum_part[by * DIM + d] = s;
        __shared__ float red[256];
        red[threadIdx.x] = s2;
        __syncthreads();
        for (int st = 128; st > 0; st >>= 1) {
            if (threadIdx.x < st) red[threadIdx.x] += red[threadIdx.x + st];
            __syncthreads();
        }
        if (threadIdx.x == 0) g_s2_part[by * 4 + bx] = red[0];
    } else {
        // ---- convert: grid-stride over X, W_skip, W_dec -----------------
        int i = (b - 1024) * blockDim.x + threadIdx.x;
        int stride = 1024 * blockDim.x;
        const int total = XU4 + WU4 + WDU4;
        for (int u = i; u < total; u += stride) {
            if (u < XU4) {
                split4((const float4*)x, u, g_Xh, g_Xl);
            } else if (u < XU4 + WU4) {
                split4((const float4*)wskip, u - XU4, g_Wh, g_Wl);
            } else {
                int v = u - XU4 - WU4;
                float4 w = ((const float4*)wdec)[v];
                __nv_bfloat162* dp = (__nv_bfloat162*)(g_Wdecb + 4 * (size_t)v);
                dp[0] = __nv_bfloat162(__float2bfloat16(w.x), __float2bfloat16(w.y));
                dp[1] = __nv_bfloat162(__float2bfloat16(w.z), __float2bfloat16(w.w));
            }
        }
    }
}

// ---------------------------------------------------------------------------
// reduce_colsum: collapse 256 row-partials -> g_colsum[1024]. grid 32 x 256.
// ---------------------------------------------------------------------------
__global__ void reduce_colsum_kernel() {
    int t = threadIdx.x;
    int lane = t & 31, seg = t >> 5;
    int col = blockIdx.x * 32 + lane;
    float s = 0.f;
#pragma unroll
    for (int r = 0; r < 32; r++)
        s += g_colsum_part[(seg * 32 + r) * DIM + col];
    __shared__ float sm[8][32];
    sm[seg][lane] = s;
    __syncthreads();
    if (seg == 0) {
        float v = sm[0][lane];
#pragma unroll
        for (int q = 1; q < 8; q++) v += sm[q][lane];
        g_colsum[col] = v;
    }
}

// ---------------------------------------------------------------------------
// Fused (warp-specialized): warps 0-7 = 4-stage cp.async HMMA skip-GEMM,
// warps 8-15 = sparse decode. Join, then decode warps do the epilogue.
// tile 128 x 128, grid (8, 32), 512 threads.
// ---------------------------------------------------------------------------
#define LDA 40                        // bf16 per smem row (80 B, conflict-free)
#define TILEB (128 * LDA * 2)         // 10240 B per operand tile
#define STAGEB (4 * TILEB)            // 40960 B per stage (AH,AL,BH,BL)
#define NSTAGE 4
#define EXLD 132
#define SM_EX   0                     // 128*132*4 = 67584 (overlays stages)
#define SM_PAIR (NSTAGE * STAGEB)     // 163840: uint2[128*16] = 16384
#define SM_RED  (SM_PAIR + 16384)     // 1024
#define SMEM_DYN (SM_PAIR + 16384 + 1024)   // 181248

__global__ void __launch_bounds__(512, 1)
fused_kernel(const float* __restrict__ y,
             const float* __restrict__ lat_acts,
             const int*   __restrict__ lat_idx,
             const float* __restrict__ b_dec,
             const float* __restrict__ post_enc,
             const float* __restrict__ pes,
             float* __restrict__ out)
{
    extern __shared__ char smem[];
    const uint32_t sb = smem_to_u32(smem);
    const int tid  = threadIdx.x;
    const int n0 = blockIdx.y * 128;
    const int d0 = blockIdx.x * 128;

    if (tid < 256) {
        // ================= GEMM group (warps 0-7) =========================
        const int wid  = tid >> 5;
        const int lane = tid & 31;
        const int wm = wid & 1;
        const int wn = wid >> 1;

        const __nv_bfloat16* gA[2] = {g_Xh + (size_t)n0 * DIM,
                                      g_Xl + (size_t)n0 * DIM};
        const __nv_bfloat16* gB[2] = {g_Wh + (size_t)d0 * DIM,
                                      g_Wl + (size_t)d0 * DIM};
        const int lrow = tid >> 1;
        const int lseg = (tid & 1) * 2;

        auto issue = [&](int kc) {
            const uint32_t base = sb + (uint32_t)((kc & 3) * STAGEB);
            const size_t gof = (size_t)lrow * DIM + kc * 32 + lseg * 8;
            const uint32_t sof = (uint32_t)(lrow * (LDA * 2) + lseg * 16);
#pragma unroll
            for (int t = 0; t < 2; t++) {
                cp16(base + t * TILEB + sof,            gA[t] + gof);
                cp16(base + t * TILEB + sof + 16,       gA[t] + gof + 8);
                cp16(base + (2 + t) * TILEB + sof,      gB[t] + gof);
                cp16(base + (2 + t) * TILEB + sof + 16, gB[t] + gof + 8);
            }
            CP_COMMIT();
        };

        float acc[4][4][4];
#pragma unroll
        for (int i = 0; i < 4; i++)
#pragma unroll
            for (int j = 0; j < 4; j++)
#pragma unroll
                for (int e = 0; e < 4; e++) acc[i][j][e] = 0.f;

        const uint32_t aoff = (uint32_t)(((((lane >> 3) & 1) * 8 + (lane & 7)) * LDA
                                          + (lane >> 4) * 8) * 2);
        const uint32_t boff = (uint32_t)(((lane & 7) * LDA + ((lane >> 3) & 1) * 8) * 2);
        const uint32_t abase = sb + aoff + (uint32_t)(wm * 64 * LDA * 2);
        const uint32_t bbase = sb + boff + (uint32_t)(wn * 32 * LDA * 2);

        issue(0); issue(1); issue(2);
        for (int kc = 0; kc < 32; kc++) {
            if (kc < 29) { issue(kc + 3); CP_WAIT3(); }
            else         { CP_WAIT0(); }
            NBAR(1, 256);
            const uint32_t stb = (uint32_t)((kc & 3) * STAGEB);
#pragma unroll
            for (int ks = 0; ks < 2; ks++) {
                const uint32_t kb = ks * 32;
                uint32_t bh[4][2], bl[4][2];
#pragma unroll
                for (int nf = 0; nf < 4; nf++) {
                    uint32_t bo = bbase + stb + (uint32_t)(nf * 8 * LDA * 2) + kb;
                    ldsm2(bh[nf], bo + 2 * TILEB);
                    ldsm2(bl[nf], bo + 3 * TILEB);
                }
#pragma unroll
                for (int mf = 0; mf < 4; mf++) {
                    uint32_t ao = abase + stb + (uint32_t)(mf * 16 * LDA * 2) + kb;
                    uint32_t ah[4], al[4];
                    ldsm4(ah, ao);
#pragma unroll
                    for (int nf = 0; nf < 4; nf++) mma16816(acc[mf][nf], ah, bh[nf]);
#pragma unroll
                    for (int nf = 0; nf < 4; nf++) mma16816(acc[mf][nf], ah, bl[nf]);
                    ldsm4(al, ao + TILEB);
#pragma unroll
                    for (int nf = 0; nf < 4; nf++) mma16816(acc[mf][nf], al, bh[nf]);
                }
            }
            NBAR(1, 256);   // reads of stage kc&3 done before next iter's issue
        }

        // spill accumulators to smem exchange buffer (overlays stage bufs)
        float* ex = (float*)(smem + SM_EX);
        int r0 = wm * 64 + (lane >> 2);
        int c0 = wn * 32 + 2 * (lane & 3);
#pragma unroll
        for (int mf = 0; mf < 4; mf++)
#pragma unroll
            for (int nf = 0; nf < 4; nf++) {
                int r = r0 + mf * 16, c = c0 + nf * 8;
                *(float2*)&ex[r * EXLD + c] =
                    make_float2(acc[mf][nf][0], acc[mf][nf][1]);
                *(float2*)&ex[(r + 8) * EXLD + c] =
                    make_float2(acc[mf][nf][2], acc[mf][nf][3]);
            }
        __syncthreads();   // join with decode group
    } else {
        // ================= Decode group (warps 8-15) ======================
        const int dtid = tid - 256;
        const int tx = dtid & 15;
        const int ty = dtid >> 4;
        uint2* pair_s = (uint2*)(smem + SM_PAIR);  // [128][16]: (byteoff, act)
        const char* wbase = (const char*)g_Wdecb + (size_t)(d0 + tx * 8) * 2;
        float c[8][8];
#pragma unroll
        for (int i = 0; i < 8; i++)
#pragma unroll
            for (int j = 0; j < 8; j++) c[i][j] = 0.f;

        for (int ph = 0; ph < 4; ph++) {
            if (ph > 0) NBAR(2, 256);
#pragma unroll
            for (int q = 0; q < 8; q++) {
                int e = dtid * 8 + q;
                int t = e >> 4, k = e & 15;
                int gi = (n0 + t) * KTOP + ph * 16 + k;
                int id = lat_idx[gi];
                float a = (lat_acts[gi] + post_enc[id]) * pes[id];
                pair_s[t * 16 + k] = make_uint2((uint32_t)id << 11,
                                                __float_as_uint(a));
            }
            NBAR(2, 256);
            for (int k = 0; k < 16; k++) {
#pragma unroll
                for (int i = 0; i < 8; i++) {
                    int t = ty * 8 + i;
                    uint2 p = pair_s[t * 16 + k];
                    float a = __uint_as_float(p.y);
                    uint4 u = __ldg((const uint4*)(wbase + p.x));
                    float2 f0 = __bfloat1622float2(*(__nv_bfloat162*)&u.x);
                    float2 f1 = __bfloat1622float2(*(__nv_bfloat162*)&u.y);
                    float2 f2 = __bfloat1622float2(*(__nv_bfloat162*)&u.z);
                    float2 f3 = __bfloat1622float2(*(__nv_bfloat162*)&u.w);
                    c[i][0] += a * f0.x; c[i][1] += a * f0.y;
                    c[i][2] += a * f1.x; c[i][3] += a * f1.y;
                    c[i][4] += a * f2.x; c[i][5] += a * f2.y;
                    c[i][6] += a * f3.x; c[i][7] += a * f3.y;
                }
            }
        }
        __syncthreads();   // join: GEMM results now in ex

        // ---- epilogue: skip + decode + b_dec -> out, err partial --------
        float* ex = (float*)(smem + SM_EX);
        float err = 0.f;
#pragma unroll
        for (int i = 0; i < 8; i++) {
            int t = ty * 8 + i;
            int n = n0 + t;
#pragma unroll
            for (int j = 0; j < 8; j += 4) {
                int d = d0 + tx * 8 + j;
                float4 bd = *(const float4*)&b_dec[d];
                float4 yv = *(const float4*)&y[(size_t)n * DIM + d];
                float4 sv = *(const float4*)&ex[t * EXLD + tx * 8 + j];
                float4 o;
                o.x = c[i][j + 0] + sv.x + bd.x;
                o.y = c[i][j + 1] + sv.y + bd.y;
                o.z = c[i][j + 2] + sv.z + bd.z;
                o.w = c[i][j + 3] + sv.w + bd.w;
                *(float4*)&out[(size_t)n * DIM + d] = o;
                float e0 = yv.x - o.x, e1 = yv.y - o.y;
                float e2 = yv.z - o.z, e3 = yv.w - o.w;
                err += e0 * e0 + e1 * e1 + e2 * e2 + e3 * e3;
            }
        }

        float* red = (float*)(smem + SM_RED);
        red[dtid] = err;
        NBAR(2, 256);
        for (int st = 128; st > 0; st >>= 1) {
            if (dtid < st) red[dtid] += red[dtid + st];
            NBAR(2, 256);
        }
        if (dtid == 0) g_err_part[blockIdx.y * gridDim.x + blockIdx.x] = red[0];
    }
}

// ---------------------------------------------------------------------------
// finalize: fvu = sum(e^2) / (sum(y^2) - sum_d colsum_d^2 / N)
// ---------------------------------------------------------------------------
__global__ void finalize_kernel(float* __restrict__ out, int fvu_idx) {
    int tid = threadIdx.x;
    float cs = g_colsum[tid];
    float csq = cs * cs;
    float s2 = g_s2_part[tid];
    float err = (tid < 256) ? g_err_part[tid] : 0.f;

    __shared__ float r1[1024], r2[1024], r3[1024];
    r1[tid] = csq; r2[tid] = s2; r3[tid] = err;
    __syncthreads();
    for (int st = 512; st > 0; st >>= 1) {
        if (tid < st) {
            r1[tid] += r1[tid + st];
            r2[tid] += r2[tid + st];
            r3[tid] += r3[tid + st];
        }
        __syncthreads();
    }
    if (tid == 0) {
        float tv = r2[0] - r1[0] / (float)NTOK;
        out[fvu_idx] = r3[0] / tv;
    }
}

// ---------------------------------------------------------------------------
extern "C" void kernel_launch(void* const* d_in, const int* in_sizes, int n_in,
                              void* d_out, int out_size)
{
    const float* x        = (const float*)d_in[0];
    const float* y        = (const float*)d_in[1];
    const float* lat_acts = (const float*)d_in[2];
    const int*   lat_idx  = (const int*)  d_in[3];
    const float* W_dec    = (const float*)d_in[4];
    const float* b_dec    = (const float*)d_in[5];
    const float* post_enc = (const float*)d_in[6];
    const float* pes      = (const float*)d_in[7];
    const float* W_skip   = (const float*)d_in[8];
    float* out = (float*)d_out;

    cudaFuncSetAttribute(fused_kernel,
                         cudaFuncAttributeMaxDynamicSharedMemorySize, SMEM_DYN);

    prep_kernel<<<2048, 256>>>(x, y, W_skip, W_dec);
    reduce_colsum_kernel<<<32, 256>>>();
    fused_kernel<<<dim3(8, 32), 512, SMEM_DYN>>>(
        y, lat_acts, lat_idx, b_dec, post_enc, pes, out);
    finalize_kernel<<<1, 1024>>>(out, out_size - 1);
}